// round 11
// baseline (speedup 1.0000x reference)
#include <cuda_runtime.h>
#include <math.h>
#include <stdint.h>

#define Bq 32
#define Vq 2048
#define Pq 64
#define Aq 8
#define Fq 72          // P + A
#define NFq 128
#define TWOF 144       // 2*F
#define NPC 64         // partial slots per batch (= 16 chunks * 4 subsets)
#define GRID 128
#define NTHR 576

#define XBS 76         // X buffer stride (tf32 words)
#define WAS 68         // phase-A W tile stride
#define WCS 76         // phase-C W tile stride
#define SFS 80         // feats tile stride (floats)

// Scratch (device globals; no allocation allowed)
__device__ uint32_t g_Xtf [Bq * Vq * Pq];     // X in tf32, 16.8 MB
__device__ uint32_t g_aggT[Bq * Vq * Aq];     // agg in tf32
__device__ uint32_t g_MT  [Bq * NFq * Aq];    // M transposed, tf32
__device__ uint32_t g_W12T[Fq * 64];          // (W1|W2)^T tf32
__device__ uint32_t g_WoutT[NFq * 64];        // Wout_top^T tf32
__device__ float    g_pmax[Bq * NPC * Aq * Fq];
__device__ float    g_psum[Bq * NPC * Aq * Fq];
__device__ unsigned g_count = 0;
__device__ unsigned g_gen   = 0;

__device__ __forceinline__ uint32_t f2tf32(float f) {
    uint32_t r; asm("cvt.rna.tf32.f32 %0, %1;" : "=r"(r) : "f"(f)); return r;
}
__device__ __forceinline__ void mma_tf32(float* d, const uint32_t* a, const uint32_t* b) {
    asm("mma.sync.aligned.m16n8k8.row.col.f32.tf32.tf32.f32 "
        "{%0,%1,%2,%3},{%4,%5,%6,%7},{%8,%9},{%0,%1,%2,%3};"
        : "+f"(d[0]), "+f"(d[1]), "+f"(d[2]), "+f"(d[3])
        : "r"(a[0]), "r"(a[1]), "r"(a[2]), "r"(a[3]), "r"(b[0]), "r"(b[1]));
}
__device__ __forceinline__ uint32_t s2u(const void* p) {
    return (uint32_t)__cvta_generic_to_shared(p);
}
__device__ __forceinline__ void ldsm4(uint32_t* r, uint32_t addr) {
    asm volatile("ldmatrix.sync.aligned.m8n8.x4.shared.b16 {%0,%1,%2,%3}, [%4];"
                 : "=r"(r[0]), "=r"(r[1]), "=r"(r[2]), "=r"(r[3]) : "r"(addr));
}
__device__ __forceinline__ void ldsm2(uint32_t* r, uint32_t addr) {
    asm volatile("ldmatrix.sync.aligned.m8n8.x2.shared.b16 {%0,%1}, [%2];"
                 : "=r"(r[0]), "=r"(r[1]) : "r"(addr));
}
__device__ __forceinline__ float ftanh(float x) {
    float e = __expf(2.0f * x);
    return 1.0f - __fdividef(2.0f, e + 1.0f);
}
__device__ __forceinline__ void cpasync16(uint32_t dst, const void* src) {
    asm volatile("cp.async.cg.shared.global [%0], [%1], 16;" :: "r"(dst), "l"(src));
}

// grid-wide barrier: generation counter; all GRID CTAs are resident (1/SM).
__device__ __forceinline__ void gbar() {
    __syncthreads();
    if (threadIdx.x == 0) {
        __threadfence();
        unsigned gen = atomicAdd(&g_gen, 0u);
        unsigned old = atomicAdd(&g_count, 1u);
        if (old == GRID - 1) {
            atomicExch(&g_count, 0u);
            __threadfence();
            atomicAdd(&g_gen, 1u);
        } else {
            while (atomicAdd(&g_gen, 0u) == gen) { }
        }
        __threadfence();
    }
    __syncthreads();
}

// smem layout (uint32 words):
//   [0, 9728)        X buffer 0  [128][XBS]
//   [9728, 19456)    X buffer 1
//   [19456, ...)     phase region:
//     A: WtA [72][WAS] (4896) | bsA (80) | sf [128][SFS] (10240)
//     B: scol [8][144]
//     C: WtC [128][WCS] (9728) | bC (128)
#define SM_R 19456
#define SM_TOTAL (SM_R + 4896 + 80 + 10240)   // 34672 words = 138688 B

__global__ void __launch_bounds__(NTHR, 1)
kfused(const float* __restrict__ X,
       const float* __restrict__ W1, const float* __restrict__ b1,
       const float* __restrict__ W2, const float* __restrict__ b2,
       const float* __restrict__ Wout, const float* __restrict__ bout,
       float* __restrict__ out) {
    extern __shared__ uint32_t smu[];
    const int tid  = threadIdx.x;
    const int bid  = blockIdx.x;
    const int wid  = tid >> 5, lane = tid & 31;
    const int lq   = lane & 3, lg = lane >> 2;

    const int rA = lane & 15;
    const int cA = (lane & 16) >> 2;
    const int rB = (lane & 7) + ((lane & 16) >> 1);
    const int cB = (lane & 8) >> 1;

    // ================= Phase 0: tf32 conversions =================
    {
        const int gtid = bid * NTHR + tid;
        const int gstep = GRID * NTHR;
        for (int i = gtid; i < (Bq * Vq * Pq) / 4; i += gstep) {
            float4 v = ((const float4*)X)[i];
            uint4 o;
            o.x = f2tf32(v.x); o.y = f2tf32(v.y);
            o.z = f2tf32(v.z); o.w = f2tf32(v.w);
            ((uint4*)g_Xtf)[i] = o;
        }
        for (int i = gtid; i < Fq * 64; i += gstep) {
            int n = i >> 6, k = i & 63;
            float v = (n < Pq) ? W1[k * Pq + n] : W2[k * Aq + (n - Pq)];
            g_W12T[i] = f2tf32(v);
        }
        for (int i = gtid; i < NFq * 64; i += gstep) {
            int n = i >> 6, k = i & 63;
            g_WoutT[i] = f2tf32(Wout[k * NFq + n]);
        }
    }
    gbar();

    // ================= Phase A: feats GEMM + partial reduce =================
    {
        uint32_t* WtA = smu + SM_R;
        float*    bsA = (float*)(smu + SM_R + 4896);
        float*    sf  = (float*)(smu + SM_R + 4976);

        // prologue group G0: WtA + X tile 0
        for (int i = tid; i < Fq * 16; i += NTHR) {
            int n = i >> 4, c = i & 15;
            cpasync16(s2u(WtA + n * WAS + c * 4), g_W12T + n * 64 + c * 4);
        }
        {
            const long row0 = (long)(bid * 4) * 128;
            for (int i = tid; i < 128 * 16; i += NTHR) {
                int r = i >> 4, c = i & 15;
                cpasync16(s2u(smu + r * XBS + c * 4), g_Xtf + (row0 + r) * 64 + c * 4);
            }
        }
        asm volatile("cp.async.commit_group;");
        if (tid < Fq) bsA[tid] = (tid < Pq) ? b1[tid] : b2[tid - Pq];

#pragma unroll
        for (int j = 0; j < 4; j++) {
            const int tile = bid * 4 + j;
            const long row0 = (long)tile * 128;
            const int b = tile >> 4, chunk = tile & 15;
            uint32_t* xb = smu + (j & 1) * 9728;

            if (j < 3) {
                const long nrow0 = (long)(tile + 1) * 128;
                uint32_t* nxb = smu + ((j + 1) & 1) * 9728;
                for (int i = tid; i < 128 * 16; i += NTHR) {
                    int r = i >> 4, c = i & 15;
                    cpasync16(s2u(nxb + r * XBS + c * 4), g_Xtf + (nrow0 + r) * 64 + c * 4);
                }
                asm volatile("cp.async.commit_group;");
                asm volatile("cp.async.wait_group 1;");
            } else {
                asm volatile("cp.async.wait_group 0;");
            }
            __syncthreads();

            float d[5][4];
            const int rg = wid & 7, wg = wid >> 3;
            if (wid < 16) {
                uint32_t aAddr = s2u(xb + (rg * 16 + rA) * XBS + cA);
#pragma unroll
                for (int nt = 0; nt < 5; nt++)
#pragma unroll
                    for (int r = 0; r < 4; r++) d[nt][r] = 0.f;

                if (wg == 0) {
                    uint32_t b0  = s2u(WtA + (0  + rB) * WAS + cB);
                    uint32_t b1a = s2u(WtA + (16 + rB) * WAS + cB);
                    uint32_t b2a = s2u(WtA + (32 + (lane & 7)) * WAS + cB);
#pragma unroll
                    for (int ks = 0; ks < 8; ks++) {
                        uint32_t a[4];
                        ldsm4(a, aAddr); aAddr += 32;
                        uint32_t bf[5][2];
                        ldsm4(&bf[0][0], b0);  b0  += 32;
                        ldsm4(&bf[2][0], b1a); b1a += 32;
                        ldsm2(bf[4], b2a);     b2a += 32;
#pragma unroll
                        for (int nt = 0; nt < 5; nt++) mma_tf32(d[nt], a, bf[nt]);
                    }
                } else {
                    uint32_t b0  = s2u(WtA + (40 + rB) * WAS + cB);
                    uint32_t b1a = s2u(WtA + (56 + rB) * WAS + cB);
#pragma unroll
                    for (int ks = 0; ks < 8; ks++) {
                        uint32_t a[4];
                        ldsm4(a, aAddr); aAddr += 32;
                        uint32_t bf[4][2];
                        ldsm4(&bf[0][0], b0);  b0  += 32;
                        ldsm4(&bf[2][0], b1a); b1a += 32;
#pragma unroll
                        for (int nt = 0; nt < 4; nt++) mma_tf32(d[nt], a, bf[nt]);
                    }
                }

                // epilogue -> sf (+ agg tf32 to global)
                const int orow = rg * 16 + lg;
                if (wg == 0) {
#pragma unroll
                    for (int nt = 0; nt < 5; nt++) {
                        const int col = nt * 8 + 2 * lq;
                        *(float2*)&sf[orow * SFS + col] =
                            make_float2(d[nt][0] + bsA[col], d[nt][1] + bsA[col + 1]);
                        *(float2*)&sf[(orow + 8) * SFS + col] =
                            make_float2(d[nt][2] + bsA[col], d[nt][3] + bsA[col + 1]);
                    }
                } else {
#pragma unroll
                    for (int nt = 0; nt < 3; nt++) {
                        const int col = (nt + 5) * 8 + 2 * lq;
                        *(float2*)&sf[orow * SFS + col] =
                            make_float2(d[nt][0] + bsA[col], d[nt][1] + bsA[col + 1]);
                        *(float2*)&sf[(orow + 8) * SFS + col] =
                            make_float2(d[nt][2] + bsA[col], d[nt][3] + bsA[col + 1]);
                    }
                    {
                        const int col = 64 + 2 * lq;
                        float e0 = __expf(-fabsf(d[3][0] + bsA[col]));
                        float e1 = __expf(-fabsf(d[3][1] + bsA[col + 1]));
                        float e2 = __expf(-fabsf(d[3][2] + bsA[col]));
                        float e3 = __expf(-fabsf(d[3][3] + bsA[col + 1]));
                        *(float2*)&sf[orow * SFS + col]       = make_float2(e0, e1);
                        *(float2*)&sf[(orow + 8) * SFS + col] = make_float2(e2, e3);
                        *(uint2*)(g_aggT + (row0 + orow) * Aq + 2 * lq) =
                            make_uint2(f2tf32(e0), f2tf32(e1));
                        *(uint2*)(g_aggT + (row0 + orow + 8) * Aq + 2 * lq) =
                            make_uint2(f2tf32(e2), f2tf32(e3));
                    }
                }
            }
            __syncthreads();

            // partial reduce: 4 subsets of 32 v; thread -> (a, f4)
            {
                const int sub = tid / 144;
                const int t   = tid % 144;
                const int a8  = t & 7;
                const int f4  = t >> 3;
                const int vbase = sub * 32;

                float4 mx = make_float4(-INFINITY, -INFINITY, -INFINITY, -INFINITY);
                float4 sv = make_float4(0.f, 0.f, 0.f, 0.f);
#pragma unroll 8
                for (int i = 0; i < 32; i++) {
                    const int v = vbase + i;
                    float e = sf[v * SFS + 64 + a8];
                    float4 x = *(float4*)&sf[v * SFS + f4 * 4];
                    float p0 = e * x.x, p1 = e * x.y, p2 = e * x.z, p3 = e * x.w;
                    mx.x = fmaxf(mx.x, p0); mx.y = fmaxf(mx.y, p1);
                    mx.z = fmaxf(mx.z, p2); mx.w = fmaxf(mx.w, p3);
                    sv.x += p0; sv.y += p1; sv.z += p2; sv.w += p3;
                }
                const int pc = chunk * 4 + sub;
                const long o = (((long)b * NPC + pc) * Aq + a8) * Fq + f4 * 4;
                *(float4*)(g_pmax + o) = mx;
                *(float4*)(g_psum + o) = sv;
            }
        }
    }
    gbar();

    // ================= Phase B: combine partials -> M (tf32, transposed) =================
    if (bid < Bq) {
        float* scol = (float*)(smu + SM_R);   // [8][144]
        const int b = bid;
        const int a = tid % Aq;
        const int f = tid / Aq;
        {
            float vmax = -INFINITY, vsum = 0.f;
            const long base = ((long)b * NPC) * Aq * Fq + a * Fq + f;
#pragma unroll 8
            for (int pc = 0; pc < NPC; pc++) {
                vmax = fmaxf(vmax, g_pmax[base + (long)pc * Aq * Fq]);
                vsum += g_psum[base + (long)pc * Aq * Fq];
            }
            scol[a * TWOF + f]      = vmax;
            scol[a * TWOF + Fq + f] = vsum * (1.0f / (float)Vq);
        }
        __syncthreads();
        for (int idx = tid; idx < Aq * NFq; idx += NTHR) {
            int aa = idx / NFq, n = idx % NFq;
            float acc = Wout[(Pq + Aq * TWOF + aa) * NFq + n];
#pragma unroll 16
            for (int g = 0; g < TWOF; g++) {
                acc = fmaf(scol[aa * TWOF + g], Wout[(Pq + aa * TWOF + g) * NFq + n], acc);
            }
            g_MT[((long)b * NFq + n) * Aq + aa] = f2tf32(acc);
        }
    }
    gbar();

    // ================= Phase C: output GEMM + tanh =================
    {
        uint32_t* WtC = smu + SM_R;                     // [128][WCS]
        float*    bC  = (float*)(smu + SM_R + 9728);    // [128]
        const int b = bid >> 2;                          // constant per CTA

        // prologue: WtC (WoutT + MT) + tile 0 X/agg
        for (int i = tid; i < NFq * 16; i += NTHR) {
            int n = i >> 4, c = i & 15;
            cpasync16(s2u(WtC + n * WCS + c * 4), g_WoutT + n * 64 + c * 4);
        }
        for (int i = tid; i < NFq * 2; i += NTHR) {
            int n = i >> 1, c = i & 1;
            cpasync16(s2u(WtC + n * WCS + 64 + c * 4),
                      g_MT + ((long)b * NFq + n) * Aq + c * 4);
        }
        {
            const long row0 = (long)(bid * 4) * 128;
            for (int i = tid; i < 128 * 18; i += NTHR) {
                int r = i / 18, s = i % 18;
                const void* src = (s < 16)
                    ? (const void*)(g_Xtf + (row0 + r) * 64 + s * 4)
                    : (const void*)(g_aggT + (row0 + r) * Aq + (s - 16) * 4);
                cpasync16(s2u(smu + r * XBS + s * 4), src);
            }
        }
        asm volatile("cp.async.commit_group;");
        if (tid < NFq) bC[tid] = bout[tid];

        const int wm = (wid >> 2) & 3, wn = wid & 3;

#pragma unroll
        for (int j = 0; j < 4; j++) {
            const int tile = bid * 4 + j;
            const long row0 = (long)tile * 128;
            uint32_t* xb = smu + (j & 1) * 9728;

            if (j < 3) {
                const long nrow0 = (long)(tile + 1) * 128;
                uint32_t* nxb = smu + ((j + 1) & 1) * 9728;
                for (int i = tid; i < 128 * 18; i += NTHR) {
                    int r = i / 18, s = i % 18;
                    const void* src = (s < 16)
                        ? (const void*)(g_Xtf + (nrow0 + r) * 64 + s * 4)
                        : (const void*)(g_aggT + (nrow0 + r) * Aq + (s - 16) * 4);
                    cpasync16(s2u(nxb + r * XBS + s * 4), src);
                }
                asm volatile("cp.async.commit_group;");
                asm volatile("cp.async.wait_group 1;");
            } else {
                asm volatile("cp.async.wait_group 0;");
            }
            __syncthreads();

            if (wid < 16) {
                uint32_t aAddr[2], bAddr[2];
#pragma unroll
                for (int mt = 0; mt < 2; mt++)
                    aAddr[mt] = s2u(xb + (wm * 32 + mt * 16 + rA) * XBS + cA);
#pragma unroll
                for (int p = 0; p < 2; p++)
                    bAddr[p] = s2u(WtC + (wn * 32 + p * 16 + rB) * WCS + cB);

                float d[2][4][4];
#pragma unroll
                for (int mt = 0; mt < 2; mt++)
#pragma unroll
                    for (int nt = 0; nt < 4; nt++)
#pragma unroll
                        for (int r = 0; r < 4; r++) d[mt][nt][r] = 0.f;

#pragma unroll
                for (int ks = 0; ks < 9; ks++) {
                    uint32_t a[2][4];
#pragma unroll
                    for (int mt = 0; mt < 2; mt++) {
                        ldsm4(a[mt], aAddr[mt]); aAddr[mt] += 32;
                    }
                    uint32_t bf[4][2];
#pragma unroll
                    for (int p = 0; p < 2; p++) {
                        ldsm4(&bf[2 * p][0], bAddr[p]); bAddr[p] += 32;
                    }
#pragma unroll
                    for (int mt = 0; mt < 2; mt++)
#pragma unroll
                        for (int nt = 0; nt < 4; nt++)
                            mma_tf32(d[mt][nt], a[mt], bf[nt]);
                }

#pragma unroll
                for (int mt = 0; mt < 2; mt++) {
                    const long r0 = row0 + wm * 32 + mt * 16 + lg;
#pragma unroll
                    for (int nt = 0; nt < 4; nt++) {
                        const int c0 = wn * 32 + nt * 8 + 2 * lq;
                        float2 o0, o1;
                        o0.x = ftanh(d[mt][nt][0] + bC[c0]);
                        o0.y = ftanh(d[mt][nt][1] + bC[c0 + 1]);
                        o1.x = ftanh(d[mt][nt][2] + bC[c0]);
                        o1.y = ftanh(d[mt][nt][3] + bC[c0 + 1]);
                        *(float2*)(out + (r0)     * NFq + c0) = o0;
                        *(float2*)(out + (r0 + 8) * NFq + c0) = o1;
                    }
                }
            }
            __syncthreads();   // protect X buffer reuse across iterations
        }
    }
}

// ---------------------------------------------------------------------------
extern "C" void kernel_launch(void* const* d_in, const int* in_sizes, int n_in,
                              void* d_out, int out_size) {
    const float* X    = (const float*)d_in[0];
    const float* W1   = (const float*)d_in[1];
    const float* b1   = (const float*)d_in[2];
    const float* W2   = (const float*)d_in[3];
    const float* b2   = (const float*)d_in[4];
    const float* Wout = (const float*)d_in[5];
    const float* bout = (const float*)d_in[6];
    float* out = (float*)d_out;

    const int smem = SM_TOTAL * 4;   // 138688 B
    cudaFuncSetAttribute(kfused, cudaFuncAttributeMaxDynamicSharedMemorySize, smem);

    kfused<<<GRID, NTHR, smem>>>(X, W1, b1, W2, b2, Wout, bout, out);
}

// round 12
// speedup vs baseline: 1.1007x; 1.1007x over previous
#include <cuda_runtime.h>
#include <math.h>
#include <stdint.h>

#define Bq 32
#define Vq 2048
#define Pq 64
#define Aq 8
#define Fq 72          // P + A
#define NFq 128
#define TWOF 144       // 2*F
#define NPC 64         // partial slots per batch (= 16 chunks * 4 subsets)

// Scratch (device globals; no allocation allowed)
__device__ uint32_t g_aggT [Bq * Vq * Aq];             // agg in tf32
__device__ uint32_t g_MT   [Bq * NFq * Aq];            // M transposed, tf32
__device__ uint32_t g_W12T [Fq * 64];                  // [n][k] tf32 (W1|W2)^T
__device__ uint32_t g_WoutT[NFq * 64];                 // [n][k] tf32 Wout_top^T
__device__ float    g_pmax [Bq * NPC * Aq * Fq];
__device__ float    g_psum [Bq * NPC * Aq * Fq];

__device__ __forceinline__ uint32_t f2tf32(float f) {
    uint32_t r; asm("cvt.rna.tf32.f32 %0, %1;" : "=r"(r) : "f"(f)); return r;
}
__device__ __forceinline__ void mma_tf32(float* d, const uint32_t* a, const uint32_t* b) {
    asm("mma.sync.aligned.m16n8k8.row.col.f32.tf32.tf32.f32 "
        "{%0,%1,%2,%3},{%4,%5,%6,%7},{%8,%9},{%0,%1,%2,%3};"
        : "+f"(d[0]), "+f"(d[1]), "+f"(d[2]), "+f"(d[3])
        : "r"(a[0]), "r"(a[1]), "r"(a[2]), "r"(a[3]), "r"(b[0]), "r"(b[1]));
}
__device__ __forceinline__ uint32_t s2u(const void* p) {
    return (uint32_t)__cvta_generic_to_shared(p);
}
__device__ __forceinline__ void ldsm4(uint32_t* r, uint32_t addr) {
    asm volatile("ldmatrix.sync.aligned.m8n8.x4.shared.b16 {%0,%1,%2,%3}, [%4];"
                 : "=r"(r[0]), "=r"(r[1]), "=r"(r[2]), "=r"(r[3]) : "r"(addr));
}
__device__ __forceinline__ void ldsm2(uint32_t* r, uint32_t addr) {
    asm volatile("ldmatrix.sync.aligned.m8n8.x2.shared.b16 {%0,%1}, [%2];"
                 : "=r"(r[0]), "=r"(r[1]) : "r"(addr));
}
__device__ __forceinline__ float ftanh(float x) {
    float e = __expf(2.0f * x);
    return 1.0f - __fdividef(2.0f, e + 1.0f);
}
__device__ __forceinline__ void cpasync16(uint32_t dst, const void* src) {
    asm volatile("cp.async.cg.shared.global [%0], [%1], 16;" :: "r"(dst), "l"(src));
}

// ---------------------------------------------------------------------------
// kT: one-time transpose + tf32 conversion of weights.
// ---------------------------------------------------------------------------
__global__ void __launch_bounds__(256)
kT(const float* __restrict__ W1, const float* __restrict__ W2,
   const float* __restrict__ Wout) {
    const int i = blockIdx.x * 256 + threadIdx.x;
    if (i < Fq * 64) {
        int n = i >> 6, k = i & 63;
        float v = (n < Pq) ? W1[k * Pq + n] : W2[k * Aq + (n - Pq)];
        g_W12T[i] = f2tf32(v);
    }
    {
        int n = i >> 6, k = i & 63;
        g_WoutT[i] = f2tf32(Wout[k * NFq + n]);
    }
}

// ---------------------------------------------------------------------------
// k1: grid 256, 2 tiles (128 rows each) per CTA, double-buffered X via
// cp.async (raw fp32, converted in-place). Wt staged once per CTA.
// 576 threads = 18 warps. MMA: warps 0-15 (8 rg x 2 ng). Reduce: 4 subsets.
// ---------------------------------------------------------------------------
#define XS1 68         // tf32 word stride of X rows
#define SFS 80         // float stride of feats tile
#define BUF1 10240     // words per X/sf buffer (128*80)
__global__ void __launch_bounds__(576)
k1(const float* __restrict__ X,
   const float* __restrict__ b1, const float* __restrict__ b2) {
    extern __shared__ uint32_t smu[];
    uint32_t* Wt = smu + 2 * BUF1;            // [72][68]
    float*    bs = (float*)(Wt + Fq * XS1);   // [72]

    const int tid = threadIdx.x;
    const int bid = blockIdx.x;
    const int wid = tid >> 5, lane = tid & 31;
    const int lq = lane & 3, lg = lane >> 2;
    const int rA = lane & 15;
    const int cA = (lane & 16) >> 2;
    const int rB = (lane & 7) + ((lane & 16) >> 1);
    const int cB = (lane & 8) >> 1;

    // prologue: group0 = Wt + X(t0); group1 = X(t1)
    for (int i = tid; i < Fq * 16; i += 576) {
        int n = i >> 4, c = i & 15;
        cpasync16(s2u(Wt + n * XS1 + c * 4), g_W12T + n * 64 + c * 4);
    }
    {
        const float* src = X + (long)(bid * 2) * 128 * Pq;
        for (int i = tid; i < 128 * 16; i += 576) {
            int r = i >> 4, c = i & 15;
            cpasync16(s2u(smu + r * XS1 + c * 4), src + r * Pq + c * 4);
        }
    }
    asm volatile("cp.async.commit_group;");
    {
        const float* src = X + (long)(bid * 2 + 1) * 128 * Pq;
        for (int i = tid; i < 128 * 16; i += 576) {
            int r = i >> 4, c = i & 15;
            cpasync16(s2u(smu + BUF1 + r * XS1 + c * 4), src + r * Pq + c * 4);
        }
    }
    asm volatile("cp.async.commit_group;");
    if (tid < Fq) bs[tid] = (tid < Pq) ? b1[tid] : b2[tid - Pq];

#pragma unroll
    for (int j = 0; j < 2; j++) {
        const int tile = bid * 2 + j;
        const long row0 = (long)tile * 128;
        const int b = tile >> 4, chunk = tile & 15;
        uint32_t* xb = smu + j * BUF1;
        float*    sf = (float*)xb;

        if (j == 0) asm volatile("cp.async.wait_group 1;");
        else        asm volatile("cp.async.wait_group 0;");
        __syncthreads();

        // in-place tf32 conversion of the raw X tile
        for (int i = tid; i < 128 * 16; i += 576) {
            uint32_t* p = xb + (i >> 4) * XS1 + (i & 15) * 4;
            float4 v = *(float4*)p;
            p[0] = f2tf32(v.x); p[1] = f2tf32(v.y);
            p[2] = f2tf32(v.z); p[3] = f2tf32(v.w);
        }
        __syncthreads();

        float d[5][4];
        const int rg = wid & 7, wg = wid >> 3;
        if (wid < 16) {
            uint32_t aAddr = s2u(xb + (rg * 16 + rA) * XS1 + cA);
#pragma unroll
            for (int nt = 0; nt < 5; nt++)
#pragma unroll
                for (int r = 0; r < 4; r++) d[nt][r] = 0.f;

            if (wg == 0) {
                uint32_t b0  = s2u(Wt + (0  + rB) * XS1 + cB);
                uint32_t b1a = s2u(Wt + (16 + rB) * XS1 + cB);
                uint32_t b2a = s2u(Wt + (32 + (lane & 7)) * XS1 + cB);
#pragma unroll
                for (int ks = 0; ks < 8; ks++) {
                    uint32_t a[4];
                    ldsm4(a, aAddr); aAddr += 32;
                    uint32_t bf[5][2];
                    ldsm4(&bf[0][0], b0);  b0  += 32;
                    ldsm4(&bf[2][0], b1a); b1a += 32;
                    ldsm2(bf[4], b2a);     b2a += 32;
#pragma unroll
                    for (int nt = 0; nt < 5; nt++) mma_tf32(d[nt], a, bf[nt]);
                }
            } else {
                uint32_t b0  = s2u(Wt + (40 + rB) * XS1 + cB);
                uint32_t b1a = s2u(Wt + (56 + rB) * XS1 + cB);
#pragma unroll
                for (int ks = 0; ks < 8; ks++) {
                    uint32_t a[4];
                    ldsm4(a, aAddr); aAddr += 32;
                    uint32_t bf[4][2];
                    ldsm4(&bf[0][0], b0);  b0  += 32;
                    ldsm4(&bf[2][0], b1a); b1a += 32;
#pragma unroll
                    for (int nt = 0; nt < 4; nt++) mma_tf32(d[nt], a, bf[nt]);
                }
            }
        }
        __syncthreads();   // all Xs reads done; safe to overwrite with sf

        if (wid < 16) {
            const int orow = rg * 16 + lg;
            if (wg == 0) {
#pragma unroll
                for (int nt = 0; nt < 5; nt++) {
                    const int col = nt * 8 + 2 * lq;
                    *(float2*)&sf[orow * SFS + col] =
                        make_float2(d[nt][0] + bs[col], d[nt][1] + bs[col + 1]);
                    *(float2*)&sf[(orow + 8) * SFS + col] =
                        make_float2(d[nt][2] + bs[col], d[nt][3] + bs[col + 1]);
                }
            } else {
#pragma unroll
                for (int nt = 0; nt < 3; nt++) {
                    const int col = (nt + 5) * 8 + 2 * lq;
                    *(float2*)&sf[orow * SFS + col] =
                        make_float2(d[nt][0] + bs[col], d[nt][1] + bs[col + 1]);
                    *(float2*)&sf[(orow + 8) * SFS + col] =
                        make_float2(d[nt][2] + bs[col], d[nt][3] + bs[col + 1]);
                }
                {   // agg cols 64..71
                    const int col = 64 + 2 * lq;
                    float e0 = __expf(-fabsf(d[3][0] + bs[col]));
                    float e1 = __expf(-fabsf(d[3][1] + bs[col + 1]));
                    float e2 = __expf(-fabsf(d[3][2] + bs[col]));
                    float e3 = __expf(-fabsf(d[3][3] + bs[col + 1]));
                    *(float2*)&sf[orow * SFS + col]       = make_float2(e0, e1);
                    *(float2*)&sf[(orow + 8) * SFS + col] = make_float2(e2, e3);
                    *(uint2*)(g_aggT + (row0 + orow) * Aq + 2 * lq) =
                        make_uint2(f2tf32(e0), f2tf32(e1));
                    *(uint2*)(g_aggT + (row0 + orow + 8) * Aq + 2 * lq) =
                        make_uint2(f2tf32(e2), f2tf32(e3));
                }
            }
        }
        __syncthreads();

        // partial reduce: 4 subsets of 32 v; thread -> (a, f4 quad)
        {
            const int sub = tid / 144;
            const int t   = tid % 144;
            const int a8  = t & 7;
            const int f4  = t >> 3;
            const int vbase = sub * 32;

            float4 mx = make_float4(-INFINITY, -INFINITY, -INFINITY, -INFINITY);
            float4 sv = make_float4(0.f, 0.f, 0.f, 0.f);
#pragma unroll 8
            for (int i = 0; i < 32; i++) {
                const int v = vbase + i;
                float e = sf[v * SFS + 64 + a8];
                float4 x = *(float4*)&sf[v * SFS + f4 * 4];
                float p0 = e * x.x, p1 = e * x.y, p2 = e * x.z, p3 = e * x.w;
                mx.x = fmaxf(mx.x, p0); mx.y = fmaxf(mx.y, p1);
                mx.z = fmaxf(mx.z, p2); mx.w = fmaxf(mx.w, p3);
                sv.x += p0; sv.y += p1; sv.z += p2; sv.w += p3;
            }
            const int pc = chunk * 4 + sub;
            const long o = (((long)b * NPC + pc) * Aq + a8) * Fq + f4 * 4;
            *(float4*)(g_pmax + o) = mx;
            *(float4*)(g_psum + o) = sv;
        }
        __syncthreads();   // sf reads done before next tile reuses nothing (safety)
    }
}

// ---------------------------------------------------------------------------
// kB2: combine partials -> collapsed[a,2F]; MT[b,n,a] tf32
// ---------------------------------------------------------------------------
__global__ void __launch_bounds__(576)
kB2(const float* __restrict__ Wout) {
    const int b = blockIdx.x;
    const int tid = threadIdx.x;
    const int a = tid % Aq;
    const int f = tid / Aq;

    __shared__ float scol[Aq][TWOF];

    {
        float vmax = -INFINITY, vsum = 0.f;
        const long base = ((long)b * NPC) * Aq * Fq + a * Fq + f;
#pragma unroll 8
        for (int pc = 0; pc < NPC; pc++) {
            vmax = fmaxf(vmax, g_pmax[base + (long)pc * Aq * Fq]);
            vsum += g_psum[base + (long)pc * Aq * Fq];
        }
        scol[a][f]      = vmax;
        scol[a][Fq + f] = vsum * (1.0f / (float)Vq);
    }
    __syncthreads();

    for (int idx = tid; idx < Aq * NFq; idx += 576) {
        int aa = idx / NFq, n = idx % NFq;
        float acc = Wout[(Pq + Aq * TWOF + aa) * NFq + n];
#pragma unroll 16
        for (int g = 0; g < TWOF; g++) {
            acc = fmaf(scol[aa][g], Wout[(Pq + aa * TWOF + g) * NFq + n], acc);
        }
        g_MT[((long)b * NFq + n) * Aq + aa] = f2tf32(acc);
    }
}

// ---------------------------------------------------------------------------
// k3: grid 256, 2 tiles (128 rows) per CTA, b constant per CTA -> Wt staged
// once. X/agg staged via cp.async (X converted in-place); tile-1 copy
// overlaps tile-0 epilogue. 512 threads = 16 warps (4m x 4n), m32 x n32.
// ---------------------------------------------------------------------------
#define XS3 76
__global__ void __launch_bounds__(512)
k3(const float* __restrict__ X, const float* __restrict__ bout,
   float* __restrict__ out) {
    extern __shared__ uint32_t sm3[];
    uint32_t* Xs = sm3;                   // [128][76]: cols 0-63 X, 64-71 agg
    uint32_t* Wt = Xs + 128 * XS3;        // [128][76]
    float*    bC = (float*)(Wt + 128 * XS3);

    const int tid = threadIdx.x;
    const int bid = blockIdx.x;
    const int b   = bid >> 3;             // (bid*2)>>4
    const int wid = tid >> 5, lane = tid & 31;
    const int wm = (wid >> 2) & 3, wn = wid & 3;
    const int lq = lane & 3, lg = lane >> 2;
    const int rA = lane & 15;
    const int cA = (lane & 16) >> 2;
    const int rB = (lane & 7) + ((lane & 16) >> 1);
    const int cB = (lane & 8) >> 1;

    // prologue: Wt (WoutT + MT) + tile-0 X/agg
    for (int i = tid; i < NFq * 16; i += 512) {
        int n = i >> 4, c = i & 15;
        cpasync16(s2u(Wt + n * XS3 + c * 4), g_WoutT + n * 64 + c * 4);
    }
    for (int i = tid; i < NFq * 2; i += 512) {
        int n = i >> 1, c = i & 1;
        cpasync16(s2u(Wt + n * XS3 + 64 + c * 4),
                  g_MT + ((long)b * NFq + n) * Aq + c * 4);
    }
    {
        const long row0 = (long)(bid * 2) * 128;
        for (int i = tid; i < 128 * 16; i += 512) {
            int r = i >> 4, c = i & 15;
            cpasync16(s2u(Xs + r * XS3 + c * 4), X + (row0 + r) * Pq + c * 4);
        }
        for (int i = tid; i < 128 * 2; i += 512) {
            int r = i >> 1, c = i & 1;
            cpasync16(s2u(Xs + r * XS3 + 64 + c * 4), g_aggT + (row0 + r) * Aq + c * 4);
        }
    }
    asm volatile("cp.async.commit_group;");
    if (tid < NFq) bC[tid] = bout[tid];

#pragma unroll
    for (int j = 0; j < 2; j++) {
        const int tile = bid * 2 + j;
        const long row0 = (long)tile * 128;

        asm volatile("cp.async.wait_group 0;");
        __syncthreads();

        // in-place tf32 conversion of raw X cols (agg already tf32)
        for (int i = tid; i < 128 * 16; i += 512) {
            uint32_t* p = Xs + (i >> 4) * XS3 + (i & 15) * 4;
            float4 v = *(float4*)p;
            p[0] = f2tf32(v.x); p[1] = f2tf32(v.y);
            p[2] = f2tf32(v.z); p[3] = f2tf32(v.w);
        }
        __syncthreads();

        uint32_t aAddr[2], bAddr[2];
#pragma unroll
        for (int mt = 0; mt < 2; mt++)
            aAddr[mt] = s2u(Xs + (wm * 32 + mt * 16 + rA) * XS3 + cA);
#pragma unroll
        for (int p = 0; p < 2; p++)
            bAddr[p] = s2u(Wt + (wn * 32 + p * 16 + rB) * XS3 + cB);

        float d[2][4][4];
#pragma unroll
        for (int mt = 0; mt < 2; mt++)
#pragma unroll
            for (int nt = 0; nt < 4; nt++)
#pragma unroll
                for (int r = 0; r < 4; r++) d[mt][nt][r] = 0.f;

#pragma unroll
        for (int ks = 0; ks < 9; ks++) {
            uint32_t a[2][4];
#pragma unroll
            for (int mt = 0; mt < 2; mt++) {
                ldsm4(a[mt], aAddr[mt]); aAddr[mt] += 32;
            }
            uint32_t bf[4][2];
#pragma unroll
            for (int p = 0; p < 2; p++) {
                ldsm4(&bf[2 * p][0], bAddr[p]); bAddr[p] += 32;
            }
#pragma unroll
            for (int mt = 0; mt < 2; mt++)
#pragma unroll
                for (int nt = 0; nt < 4; nt++)
                    mma_tf32(d[mt][nt], a[mt], bf[nt]);
        }
        __syncthreads();   // Xs reads done

        if (j == 0) {      // prefetch tile 1 X/agg; overlaps epilogue below
            const long nrow0 = (long)(tile + 1) * 128;
            for (int i = tid; i < 128 * 16; i += 512) {
                int r = i >> 4, c = i & 15;
                cpasync16(s2u(Xs + r * XS3 + c * 4), X + (nrow0 + r) * Pq + c * 4);
            }
            for (int i = tid; i < 128 * 2; i += 512) {
                int r = i >> 1, c = i & 1;
                cpasync16(s2u(Xs + r * XS3 + 64 + c * 4), g_aggT + (nrow0 + r) * Aq + c * 4);
            }
            asm volatile("cp.async.commit_group;");
        }

#pragma unroll
        for (int mt = 0; mt < 2; mt++) {
            const long r0 = row0 + wm * 32 + mt * 16 + lg;
#pragma unroll
            for (int nt = 0; nt < 4; nt++) {
                const int c0 = wn * 32 + nt * 8 + 2 * lq;
                float2 o0, o1;
                o0.x = ftanh(d[mt][nt][0] + bC[c0]);
                o0.y = ftanh(d[mt][nt][1] + bC[c0 + 1]);
                o1.x = ftanh(d[mt][nt][2] + bC[c0]);
                o1.y = ftanh(d[mt][nt][3] + bC[c0 + 1]);
                *(float2*)(out + (r0)     * NFq + c0) = o0;
                *(float2*)(out + (r0 + 8) * NFq + c0) = o1;
            }
        }
    }
}

// ---------------------------------------------------------------------------
extern "C" void kernel_launch(void* const* d_in, const int* in_sizes, int n_in,
                              void* d_out, int out_size) {
    const float* X    = (const float*)d_in[0];
    const float* W1   = (const float*)d_in[1];
    const float* b1   = (const float*)d_in[2];
    const float* W2   = (const float*)d_in[3];
    const float* b2   = (const float*)d_in[4];
    const float* Wout = (const float*)d_in[5];
    const float* bout = (const float*)d_in[6];
    float* out = (float*)d_out;

    const int smem1 = (2 * BUF1 + Fq * XS1 + 80) * 4;          // ~101.8 KB
    const int smem3 = (128 * XS3 * 2) * 4 + NFq * 4;           // ~78.3 KB
    cudaFuncSetAttribute(k1, cudaFuncAttributeMaxDynamicSharedMemorySize, smem1);
    cudaFuncSetAttribute(k3, cudaFuncAttributeMaxDynamicSharedMemorySize, smem3);

    kT<<<32, 256>>>(W1, W2, Wout);

    k1<<<(Bq * Vq) / 256, 576, smem1>>>(X, b1, b2);

    kB2<<<Bq, 576>>>(Wout);

    k3<<<(Bq * Vq) / 256, 512, smem3>>>(X, bout, out);
}